// round 14
// baseline (speedup 1.0000x reference)
#include <cuda_runtime.h>
#include <cstdint>

// Problem constants
#define TT    10
#define NH    12
#define DH    32
#define DIM   384
#define NB    16384
#define MROWS (NB * TT)        // 163840
#define NQKV  1152
#define KDIM  384
#define BK    32
#define NCHUNK (KDIM / BK)     // 12
#define NSTAGE 3

// Scratch (device globals — allocation-free per harness rules)
__device__ float    g_qkv[(size_t)MROWS * NQKV];   // [163840, 1152]
__device__ float    g_att[(size_t)MROWS * DIM];    // [163840, 384] (tf32 bits)
__device__ uint32_t g_wq[NQKV * KDIM];             // qkv_w tf32 bits
__device__ uint32_t g_wp[DIM * KDIM];              // proj_w tf32 bits

__device__ __forceinline__ uint32_t f2tf(float x) {
    uint32_t r;
    asm("cvt.rna.tf32.f32 %0, %1;" : "=r"(r) : "f"(x));
    return r;
}

__device__ __forceinline__ uint32_t smem_u32(const void* p) {
    uint32_t a;
    asm("{ .reg .u64 t; cvta.to.shared.u64 t, %1; cvt.u32.u64 %0, t; }"
        : "=r"(a) : "l"(p));
    return a;
}

__device__ __forceinline__ void cp16(uint32_t dst, const void* src) {
    asm volatile("cp.async.cg.shared.global [%0], [%1], 16;"
                 :: "r"(dst), "l"(src) : "memory");
}
#define CP_COMMIT()  asm volatile("cp.async.commit_group;" ::: "memory")
#define CP_WAIT(n)   asm volatile("cp.async.wait_group %0;" :: "n"(n) : "memory")

#define LDSM4(r0, r1, r2, r3, addr) \
    asm volatile("ldmatrix.sync.aligned.m8n8.x4.shared.b16 {%0,%1,%2,%3}, [%4];" \
                 : "=r"(r0), "=r"(r1), "=r"(r2), "=r"(r3) : "r"(addr))

__device__ __forceinline__ void mma_16x8x8(float* c, const uint32_t* a, const uint32_t* b) {
    asm volatile(
        "mma.sync.aligned.m16n8k8.row.col.f32.tf32.tf32.f32 "
        "{%0,%1,%2,%3}, {%4,%5,%6,%7}, {%8,%9}, {%0,%1,%2,%3};"
        : "+f"(c[0]), "+f"(c[1]), "+f"(c[2]), "+f"(c[3])
        : "r"(a[0]), "r"(a[1]), "r"(a[2]), "r"(a[3]),
          "r"(b[0]), "r"(b[1]));
}

// Pre-pass: convert both weight matrices to tf32 (RNA) bit patterns.
__global__ void __launch_bounds__(256)
conv_w(const float* __restrict__ wq, const float* __restrict__ wp)
{
    const int nq = NQKV * KDIM / 4;
    const int np = DIM * KDIM / 4;
    int i = blockIdx.x * 256 + threadIdx.x;
    if (i < nq) {
        float4 v = reinterpret_cast<const float4*>(wq)[i];
        reinterpret_cast<uint4*>(g_wq)[i] =
            make_uint4(f2tf(v.x), f2tf(v.y), f2tf(v.z), f2tf(v.w));
    } else if (i < nq + np) {
        int j = i - nq;
        float4 v = reinterpret_cast<const float4*>(wp)[j];
        reinterpret_cast<uint4*>(g_wp)[j] =
            make_uint4(f2tf(v.x), f2tf(v.y), f2tf(v.z), f2tf(v.w));
    }
}

// ===== TF32 GEMM: CTA tile 256x128, 512 threads, 16 warps (4m x 4n), warp tile 64x32 =====
// C[M,N] = A[M,K] * Btf[N,K]^T + bias[N]
//   CVT_A: apply cvt.rna to A fragments after LDSM (A stored as raw fp32).
// BK=32, 3-stage cp.async. Row stride 36 words (144B).
#define A_BYTES     36864u          // 256 * 144
#define B_BYTES     18432u          // 128 * 144
#define STAGE_BYTES 55296u          // A + B
#define ROWB        144u

template<bool CVT_A>
__global__ void __launch_bounds__(512, 1)
gemm_tf32(const float* __restrict__ A, const uint32_t* __restrict__ Btf,
          const float* __restrict__ bias, float* __restrict__ C, int N)
{
    extern __shared__ uint32_t dyn[];
    const uint32_t smem_base = smem_u32(dyn);

    const int tid  = threadIdx.x;
    const int warp = tid >> 5;
    const int lane = tid & 31;
    const int lq   = lane >> 2;
    const int lr   = lane & 3;
    const int wm   = (warp >> 2) * 64;   // 0,64,128,192
    const int wn   = (warp & 3) * 32;    // 0,32,64,96
    const size_t mblk = (size_t)blockIdx.y * 256;
    const int    nblk = blockIdx.x * 128;

    // ldmatrix per-lane address offsets (bytes)
    const uint32_t a_off = (uint32_t)(lane & 15) * ROWB + (uint32_t)(lane >> 4) * 16u;
    const uint32_t b_off = ((uint32_t)(lane & 7) + (uint32_t)((lane >> 4) << 3)) * ROWB
                         + (uint32_t)(((lane >> 3) & 1) << 4);

    float acc[4][4][4];
    #pragma unroll
    for (int i = 0; i < 4; i++)
        #pragma unroll
        for (int j = 0; j < 4; j++)
            #pragma unroll
            for (int r = 0; r < 4; r++)
                acc[i][j][r] = 0.0f;

    auto prefetch = [&](int stage, int c) {
        const uint32_t aBase = smem_base + (uint32_t)stage * STAGE_BYTES;
        const uint32_t bBase = aBase + A_BYTES;
        const int kb = c * BK;
        // A: 256 rows x 8 x 16B = 2048 cp16 / 512 thr = 4 each
        #pragma unroll
        for (int i = 0; i < 4; i++) {
            int idx = tid + i * 512;
            int row = idx >> 3;              // 0..255
            int kc  = (idx & 7) << 2;
            cp16(aBase + (uint32_t)row * ROWB + (uint32_t)kc * 4u,
                 A + (mblk + row) * KDIM + kb + kc);
        }
        // B: 128 rows x 8 x 16B = 1024 cp16 / 512 thr = 2 each
        #pragma unroll
        for (int i = 0; i < 2; i++) {
            int idx = tid + i * 512;
            int row = idx >> 3;              // 0..127
            int kc  = (idx & 7) << 2;
            cp16(bBase + (uint32_t)row * ROWB + (uint32_t)kc * 4u,
                 Btf + (size_t)(nblk + row) * KDIM + kb + kc);
        }
        CP_COMMIT();
    };

    prefetch(0, 0);
    prefetch(1, 1);

    int s = 0;
    for (int c = 0; c < NCHUNK; c++) {
        if (c < NCHUNK - 1) { CP_WAIT(1); } else { CP_WAIT(0); }
        __syncthreads();

        if (c + 2 < NCHUNK) {
            int ps = s + 2; if (ps >= NSTAGE) ps -= NSTAGE;
            prefetch(ps, c + 2);
        }

        const uint32_t aStage = smem_base + (uint32_t)s * STAGE_BYTES;
        const uint32_t aAddr0 = aStage + (uint32_t)wm * ROWB + a_off;
        const uint32_t bAddr0 = aStage + A_BYTES + (uint32_t)wn * ROWB + b_off;

        #pragma unroll
        for (int ks = 0; ks < 4; ks++) {
            const uint32_t k0b = (uint32_t)ks * 32u;
            uint32_t af[4][4], bf[4][2];
            #pragma unroll
            for (int mf = 0; mf < 4; mf++) {
                LDSM4(af[mf][0], af[mf][1], af[mf][2], af[mf][3],
                      aAddr0 + (uint32_t)mf * (16u * ROWB) + k0b);
            }
            #pragma unroll
            for (int p = 0; p < 2; p++) {
                LDSM4(bf[2*p][0], bf[2*p][1], bf[2*p+1][0], bf[2*p+1][1],
                      bAddr0 + (uint32_t)p * (16u * ROWB) + k0b);
            }
            if (CVT_A) {
                #pragma unroll
                for (int mf = 0; mf < 4; mf++)
                    #pragma unroll
                    for (int r = 0; r < 4; r++)
                        af[mf][r] = f2tf(__uint_as_float(af[mf][r]));
            }
            #pragma unroll
            for (int mf = 0; mf < 4; mf++)
                #pragma unroll
                for (int nf = 0; nf < 4; nf++)
                    mma_16x8x8(acc[mf][nf], af[mf], bf[nf]);
        }

        if (++s >= NSTAGE) s -= NSTAGE;
    }

    // Epilogue: bias add + float2 stores
    #pragma unroll
    for (int mf = 0; mf < 4; mf++) {
        size_t row = mblk + wm + mf * 16 + lq;
        #pragma unroll
        for (int nf = 0; nf < 4; nf++) {
            int col = nblk + wn + nf * 8 + lr * 2;
            float b0 = __ldg(bias + col);
            float b1 = __ldg(bias + col + 1);
            float2 v0 = make_float2(acc[mf][nf][0] + b0, acc[mf][nf][1] + b1);
            float2 v1 = make_float2(acc[mf][nf][2] + b0, acc[mf][nf][3] + b1);
            *reinterpret_cast<float2*>(C + row * (size_t)N + col)       = v0;
            *reinterpret_cast<float2*>(C + (row + 8) * (size_t)N + col) = v1;
        }
    }
}

// ======================= fused attention (256 threads, 8 units/CTA) =======================
__global__ void __launch_bounds__(256)
attn_kernel(const float* __restrict__ bias_table)
{
    __shared__ float sQ[8][TT][33];
    __shared__ float sK[8][TT][33];
    __shared__ float sV[8][TT][33];
    __shared__ float sP[8][TT * TT];
    __shared__ float sB[(2 * TT - 1) * NH];

    const int w    = threadIdx.x >> 5;
    const int lane = threadIdx.x & 31;

    for (int i = threadIdx.x; i < (2 * TT - 1) * NH; i += 256)
        sB[i] = bias_table[i];

    const int unit = blockIdx.x * 8 + w;
    const int b = unit / NH;
    const int h = unit - b * NH;

    const float* base = g_qkv + (size_t)(b * TT) * NQKV + h * DH;

    __syncthreads();

    #pragma unroll
    for (int t = 0; t < TT; t++) {
        sQ[w][t][lane] = base[t * NQKV + lane];
        sK[w][t][lane] = base[t * NQKV + DIM + lane];
        sV[w][t][lane] = base[t * NQKV + 2 * DIM + lane];
    }
    __syncwarp();

    const float scale = 0.17677669529663687f;
    for (int e = lane; e < TT * TT; e += 32) {
        int t = e / TT;
        int j = e - t * TT;
        float a = 0.0f;
        #pragma unroll
        for (int d = 0; d < DH; d++)
            a += sQ[w][t][d] * sK[w][j][d];
        sP[w][e] = a * scale + sB[(t - j + TT - 1) * NH + h];
    }
    __syncwarp();

    if (lane < TT) {
        float row[TT];
        float m = -1e30f;
        #pragma unroll
        for (int j = 0; j < TT; j++) { row[j] = sP[w][lane * TT + j]; m = fmaxf(m, row[j]); }
        float s = 0.0f;
        #pragma unroll
        for (int j = 0; j < TT; j++) { row[j] = __expf(row[j] - m); s += row[j]; }
        float inv = 1.0f / s;
        #pragma unroll
        for (int j = 0; j < TT; j++) sP[w][lane * TT + j] = row[j] * inv;
    }
    __syncwarp();

    float* outp = g_att + (size_t)(b * TT) * DIM + h * DH;
    #pragma unroll
    for (int t = 0; t < TT; t++) {
        float a = 0.0f;
        #pragma unroll
        for (int j = 0; j < TT; j++)
            a += sP[w][t * TT + j] * sV[w][j][lane];
        outp[t * DIM + lane] = __uint_as_float(f2tf(a));   // tf32 bits for GEMM2
    }
}

extern "C" void kernel_launch(void* const* d_in, const int* in_sizes, int n_in,
                              void* d_out, int out_size)
{
    (void)in_sizes; (void)n_in; (void)out_size;
    const float* x      = (const float*)d_in[0];   // [16384,10,384]
    const float* qkv_w  = (const float*)d_in[1];   // [1152,384]
    const float* qkv_b  = (const float*)d_in[2];   // [1152]
    const float* proj_w = (const float*)d_in[3];   // [384,384]
    const float* proj_b = (const float*)d_in[4];   // [384]
    const float* bias_t = (const float*)d_in[5];   // [19,12]
    float* out = (float*)d_out;                    // [163840,384]

    void* pq = nullptr; void* pa = nullptr;
    void* pwq = nullptr; void* pwp = nullptr;
    cudaGetSymbolAddress(&pq, g_qkv);
    cudaGetSymbolAddress(&pa, g_att);
    cudaGetSymbolAddress(&pwq, g_wq);
    cudaGetSymbolAddress(&pwp, g_wp);

    const int smem_bytes = NSTAGE * (int)STAGE_BYTES;   // 165888
    cudaFuncSetAttribute(gemm_tf32<true>,  cudaFuncAttributeMaxDynamicSharedMemorySize, smem_bytes);
    cudaFuncSetAttribute(gemm_tf32<false>, cudaFuncAttributeMaxDynamicSharedMemorySize, smem_bytes);

    // 0) Pre-convert weights to tf32 bits
    const int nconv = (NQKV * KDIM + DIM * KDIM) / 4;
    conv_w<<<(nconv + 255) / 256, 256>>>(qkv_w, proj_w);

    // 1) qkv = x @ qkv_w^T + qkv_b   (A = raw fp32 -> cvt in-loop)
    dim3 g1(NQKV / 128, MROWS / 256);   // (9, 640)
    gemm_tf32<true><<<g1, 512, smem_bytes>>>(x, (const uint32_t*)pwq, qkv_b, (float*)pq, NQKV);

    // 2) attention, 8 units per 256-thread CTA
    attn_kernel<<<(NB * NH) / 8, 256>>>(bias_t);

    // 3) out = att @ proj_w^T + proj_b   (A already tf32 bits)
    dim3 g2(DIM / 128, MROWS / 256);    // (3, 640)
    gemm_tf32<false><<<g2, 512, smem_bytes>>>((const float*)pa, (const uint32_t*)pwp, proj_b, out, DIM);
}

// round 15
// speedup vs baseline: 1.0777x; 1.0777x over previous
#include <cuda_runtime.h>
#include <cstdint>

// Problem constants
#define TT    10
#define NH    12
#define DH    32
#define DIM   384
#define NB    16384
#define MROWS (NB * TT)        // 163840
#define NQKV  1152
#define KDIM  384
#define BK    32
#define NCHUNK (KDIM / BK)     // 12
#define NSTAGE 3

// Scratch (device globals — allocation-free per harness rules)
__device__ float    g_qkv[(size_t)MROWS * NQKV];   // [163840, 1152]
__device__ float    g_att[(size_t)MROWS * DIM];    // [163840, 384] (tf32 bits)
__device__ uint32_t g_wq[NQKV * KDIM];             // qkv_w tf32 bits
__device__ uint32_t g_wp[DIM * KDIM];              // proj_w tf32 bits

__device__ __forceinline__ uint32_t f2tf(float x) {
    uint32_t r;
    asm("cvt.rna.tf32.f32 %0, %1;" : "=r"(r) : "f"(x));
    return r;
}

__device__ __forceinline__ uint32_t smem_u32(const void* p) {
    uint32_t a;
    asm("{ .reg .u64 t; cvta.to.shared.u64 t, %1; cvt.u32.u64 %0, t; }"
        : "=r"(a) : "l"(p));
    return a;
}

__device__ __forceinline__ void cp16(uint32_t dst, const void* src) {
    asm volatile("cp.async.cg.shared.global [%0], [%1], 16;"
                 :: "r"(dst), "l"(src) : "memory");
}
#define CP_COMMIT()  asm volatile("cp.async.commit_group;" ::: "memory")
#define CP_WAIT(n)   asm volatile("cp.async.wait_group %0;" :: "n"(n) : "memory")

#define LDSM4(r0, r1, r2, r3, addr) \
    asm volatile("ldmatrix.sync.aligned.m8n8.x4.shared.b16 {%0,%1,%2,%3}, [%4];" \
                 : "=r"(r0), "=r"(r1), "=r"(r2), "=r"(r3) : "r"(addr))

__device__ __forceinline__ void mma_16x8x8(float* c, const uint32_t* a, const uint32_t* b) {
    asm volatile(
        "mma.sync.aligned.m16n8k8.row.col.f32.tf32.tf32.f32 "
        "{%0,%1,%2,%3}, {%4,%5,%6,%7}, {%8,%9}, {%0,%1,%2,%3};"
        : "+f"(c[0]), "+f"(c[1]), "+f"(c[2]), "+f"(c[3])
        : "r"(a[0]), "r"(a[1]), "r"(a[2]), "r"(a[3]),
          "r"(b[0]), "r"(b[1]));
}

// Pre-pass: convert both weight matrices to tf32 (RNA) bit patterns.
__global__ void __launch_bounds__(256)
conv_w(const float* __restrict__ wq, const float* __restrict__ wp)
{
    const int nq = NQKV * KDIM / 4;
    const int np = DIM * KDIM / 4;
    int i = blockIdx.x * 256 + threadIdx.x;
    if (i < nq) {
        float4 v = reinterpret_cast<const float4*>(wq)[i];
        reinterpret_cast<uint4*>(g_wq)[i] =
            make_uint4(f2tf(v.x), f2tf(v.y), f2tf(v.z), f2tf(v.w));
    } else if (i < nq + np) {
        int j = i - nq;
        float4 v = reinterpret_cast<const float4*>(wp)[j];
        reinterpret_cast<uint4*>(g_wp)[j] =
            make_uint4(f2tf(v.x), f2tf(v.y), f2tf(v.z), f2tf(v.w));
    }
}

// ====== TF32 GEMM (R12 best config): 128 threads, 4 warps (2x2), warp tile 64x64 ======
// C[M,N] = A[M,K] * Btf[N,K]^T + bias[N]
//   CVT_A: apply cvt.rna to A fragments after LDSM (A stored as raw fp32).
// CTA tile 128x128, BK=32, 3-stage cp.async. Row stride 36 words (144B).
#define STAGE_BYTES 36864u          // (128*36*4) * 2  (A half + B half)
#define AB_BYTES    18432u          // 128 * 36 * 4
#define ROWB        144u            // bytes per smem row

template<bool CVT_A>
__global__ void __launch_bounds__(128, 2)
gemm_tf32(const float* __restrict__ A, const uint32_t* __restrict__ Btf,
          const float* __restrict__ bias, float* __restrict__ C, int N)
{
    extern __shared__ uint32_t dyn[];
    const uint32_t smem_base = smem_u32(dyn);

    const int tid  = threadIdx.x;
    const int warp = tid >> 5;
    const int lane = tid & 31;
    const int lq   = lane >> 2;
    const int lr   = lane & 3;
    const int wm   = (warp >> 1) * 64;
    const int wn   = (warp & 1) * 64;
    const size_t mblk = (size_t)blockIdx.y * 128;
    const int    nblk = blockIdx.x * 128;

    const uint32_t a_off = (uint32_t)(lane & 15) * ROWB + (uint32_t)(lane >> 4) * 16u;
    const uint32_t b_off = ((uint32_t)(lane & 7) + (uint32_t)((lane >> 4) << 3)) * ROWB
                         + (uint32_t)(((lane >> 3) & 1) << 4);

    float acc[4][8][4];
    #pragma unroll
    for (int i = 0; i < 4; i++)
        #pragma unroll
        for (int j = 0; j < 8; j++)
            #pragma unroll
            for (int r = 0; r < 4; r++)
                acc[i][j][r] = 0.0f;

    auto prefetch = [&](int stage, int c) {
        const uint32_t aBase = smem_base + (uint32_t)stage * STAGE_BYTES;
        const uint32_t bBase = aBase + AB_BYTES;
        const int kb = c * BK;
        #pragma unroll
        for (int i = 0; i < 8; i++) {
            int idx = tid + i * 128;
            int row = idx >> 3;
            int kc  = (idx & 7) << 2;
            uint32_t off = (uint32_t)row * ROWB + (uint32_t)kc * 4u;
            cp16(aBase + off, A + (mblk + row) * KDIM + kb + kc);
            cp16(bBase + off, Btf + (size_t)(nblk + row) * KDIM + kb + kc);
        }
        CP_COMMIT();
    };

    prefetch(0, 0);
    prefetch(1, 1);

    int s = 0;
    for (int c = 0; c < NCHUNK; c++) {
        if (c < NCHUNK - 1) { CP_WAIT(1); } else { CP_WAIT(0); }
        __syncthreads();

        if (c + 2 < NCHUNK) {
            int ps = s + 2; if (ps >= NSTAGE) ps -= NSTAGE;
            prefetch(ps, c + 2);
        }

        const uint32_t aStage = smem_base + (uint32_t)s * STAGE_BYTES;
        const uint32_t aAddr0 = aStage + (uint32_t)wm * ROWB + a_off;
        const uint32_t bAddr0 = aStage + AB_BYTES + (uint32_t)wn * ROWB + b_off;

        #pragma unroll
        for (int ks = 0; ks < 4; ks++) {
            const uint32_t k0b = (uint32_t)ks * 32u;
            uint32_t af[4][4], bf[8][2];
            #pragma unroll
            for (int mf = 0; mf < 4; mf++) {
                LDSM4(af[mf][0], af[mf][1], af[mf][2], af[mf][3],
                      aAddr0 + (uint32_t)mf * (16u * ROWB) + k0b);
            }
            #pragma unroll
            for (int p = 0; p < 4; p++) {
                LDSM4(bf[2*p][0], bf[2*p][1], bf[2*p+1][0], bf[2*p+1][1],
                      bAddr0 + (uint32_t)p * (16u * ROWB) + k0b);
            }
            if (CVT_A) {
                #pragma unroll
                for (int mf = 0; mf < 4; mf++)
                    #pragma unroll
                    for (int r = 0; r < 4; r++)
                        af[mf][r] = f2tf(__uint_as_float(af[mf][r]));
            }
            #pragma unroll
            for (int mf = 0; mf < 4; mf++)
                #pragma unroll
                for (int nf = 0; nf < 8; nf++)
                    mma_16x8x8(acc[mf][nf], af[mf], bf[nf]);
        }

        if (++s >= NSTAGE) s -= NSTAGE;
    }

    // Epilogue: bias add + float2 stores
    #pragma unroll
    for (int mf = 0; mf < 4; mf++) {
        size_t row = mblk + wm + mf * 16 + lq;
        #pragma unroll
        for (int nf = 0; nf < 8; nf++) {
            int col = nblk + wn + nf * 8 + lr * 2;
            float b0 = __ldg(bias + col);
            float b1 = __ldg(bias + col + 1);
            float2 v0 = make_float2(acc[mf][nf][0] + b0, acc[mf][nf][1] + b1);
            float2 v1 = make_float2(acc[mf][nf][2] + b0, acc[mf][nf][3] + b1);
            *reinterpret_cast<float2*>(C + row * (size_t)N + col)       = v0;
            *reinterpret_cast<float2*>(C + (row + 8) * (size_t)N + col) = v1;
        }
    }
}

// ======================= fused attention (float4 staging, float2 dots) =======================
__global__ void __launch_bounds__(128)
attn_kernel(const float* __restrict__ bias_table)
{
    // [unit][which(q,k,v)][t][36]  -- stride 36 keeps float4 STS phases conflict-free
    __shared__ float sQKV[4][3][TT][36];
    __shared__ float sP[4][TT * TT];
    __shared__ float sB[(2 * TT - 1) * NH];

    const int w    = threadIdx.x >> 5;
    const int lane = threadIdx.x & 31;

    for (int i = threadIdx.x; i < (2 * TT - 1) * NH; i += 128)
        sB[i] = bias_table[i];

    const int unit = blockIdx.x * 4 + w;
    const int b = unit / NH;
    const int h = unit - b * NH;

    const float* base = g_qkv + (size_t)(b * TT) * NQKV + h * DH;

    __syncthreads();   // sB ready

    // Stage q,k,v: 240 float4 tasks per warp (30 rows x 8 lanes)
    #pragma unroll
    for (int i = 0; i < 8; i++) {
        int task = i * 32 + lane;
        if (task < 240) {
            int row   = task >> 3;          // 0..29
            int c     = task & 7;           // 0..7
            int which = row / 10;           // 0=q,1=k,2=v
            int t     = row - which * 10;
            float4 v4 = *reinterpret_cast<const float4*>(base + t * NQKV + which * DIM + c * 4);
            *reinterpret_cast<float4*>(&sQKV[w][which][t][c * 4]) = v4;
        }
    }
    __syncwarp();

    // Scores + bias (float2 dot products)
    const float scale = 0.17677669529663687f;  // 32^-0.5
    #pragma unroll
    for (int e = lane; e < TT * TT; e += 32) {
        int t = e / TT;
        int j = e - t * TT;
        const float2* q2 = reinterpret_cast<const float2*>(&sQKV[w][0][t][0]);
        const float2* k2 = reinterpret_cast<const float2*>(&sQKV[w][1][j][0]);
        float a0 = 0.0f, a1 = 0.0f;
        #pragma unroll
        for (int d = 0; d < 16; d++) {
            float2 qv = q2[d];
            float2 kv = k2[d];
            a0 += qv.x * kv.x;
            a1 += qv.y * kv.y;
        }
        sP[w][e] = (a0 + a1) * scale + sB[(t - j + TT - 1) * NH + h];
    }
    __syncwarp();

    // Softmax per row (lanes 0..9)
    if (lane < TT) {
        float row[TT];
        float m = -1e30f;
        #pragma unroll
        for (int j = 0; j < TT; j++) { row[j] = sP[w][lane * TT + j]; m = fmaxf(m, row[j]); }
        float s = 0.0f;
        #pragma unroll
        for (int j = 0; j < TT; j++) { row[j] = __expf(row[j] - m); s += row[j]; }
        float inv = 1.0f / s;
        #pragma unroll
        for (int j = 0; j < TT; j++) sP[w][lane * TT + j] = row[j] * inv;
    }
    __syncwarp();

    // out[t][d] = sum_j p[t][j] * v[j][d]; lane = d
    float* outp = g_att + (size_t)(b * TT) * DIM + h * DH;
    #pragma unroll
    for (int t = 0; t < TT; t++) {
        float a = 0.0f;
        #pragma unroll
        for (int j = 0; j < TT; j++)
            a += sP[w][t * TT + j] * sQKV[w][2][j][lane];
        outp[t * DIM + lane] = __uint_as_float(f2tf(a));   // tf32 bits for GEMM2
    }
}

extern "C" void kernel_launch(void* const* d_in, const int* in_sizes, int n_in,
                              void* d_out, int out_size)
{
    (void)in_sizes; (void)n_in; (void)out_size;
    const float* x      = (const float*)d_in[0];   // [16384,10,384]
    const float* qkv_w  = (const float*)d_in[1];   // [1152,384]
    const float* qkv_b  = (const float*)d_in[2];   // [1152]
    const float* proj_w = (const float*)d_in[3];   // [384,384]
    const float* proj_b = (const float*)d_in[4];   // [384]
    const float* bias_t = (const float*)d_in[5];   // [19,12]
    float* out = (float*)d_out;                    // [163840,384]

    void* pq = nullptr; void* pa = nullptr;
    void* pwq = nullptr; void* pwp = nullptr;
    cudaGetSymbolAddress(&pq, g_qkv);
    cudaGetSymbolAddress(&pa, g_att);
    cudaGetSymbolAddress(&pwq, g_wq);
    cudaGetSymbolAddress(&pwp, g_wp);

    const int smem_bytes = NSTAGE * (int)STAGE_BYTES;   // 110592
    cudaFuncSetAttribute(gemm_tf32<true>,  cudaFuncAttributeMaxDynamicSharedMemorySize, smem_bytes);
    cudaFuncSetAttribute(gemm_tf32<false>, cudaFuncAttributeMaxDynamicSharedMemorySize, smem_bytes);

    // 0) Pre-convert weights to tf32 bits
    const int nconv = (NQKV * KDIM + DIM * KDIM) / 4;
    conv_w<<<(nconv + 255) / 256, 256>>>(qkv_w, proj_w);

    // 1) qkv = x @ qkv_w^T + qkv_b   (A = raw fp32 -> cvt in-loop)
    dim3 g1(NQKV / 128, MROWS / 128);   // (9, 1280)
    gemm_tf32<true><<<g1, 128, smem_bytes>>>(x, (const uint32_t*)pwq, qkv_b, (float*)pq, NQKV);

    // 2) attention, one warp per (b, h); writes tf32 bits
    attn_kernel<<<(NB * NH) / 4, 128>>>(bias_t);

    // 3) out = att @ proj_w^T + proj_b   (A already tf32 bits)
    dim3 g2(DIM / 128, MROWS / 128);    // (3, 1280)
    gemm_tf32<false><<<g2, 128, smem_bytes>>>((const float*)pa, (const uint32_t*)pwp, proj_b, out, DIM);
}

// round 16
// speedup vs baseline: 1.6436x; 1.5250x over previous
#include <cuda_runtime.h>
#include <cuda_fp16.h>
#include <cstdint>

// Problem constants
#define TT    10
#define NH    12
#define DH    32
#define DIM   384
#define NB    16384
#define MROWS (NB * TT)        // 163840
#define NQKV  1152
#define KDIM  384
#define BK    64
#define NCHUNK (KDIM / BK)     // 6
#define NSTAGE 3

// Scratch (device globals — allocation-free per harness rules)
__device__ float  g_qkv[(size_t)MROWS * NQKV];   // [163840, 1152] fp32 (attention reads this)
__device__ __half g_xh [(size_t)MROWS * KDIM];   // x converted to fp16
__device__ __half g_ath[(size_t)MROWS * DIM];    // attention output, fp16
__device__ __half g_wqh[NQKV * KDIM];            // qkv_w fp16
__device__ __half g_wph[DIM * KDIM];             // proj_w fp16

__device__ __forceinline__ uint32_t smem_u32(const void* p) {
    uint32_t a;
    asm("{ .reg .u64 t; cvta.to.shared.u64 t, %1; cvt.u32.u64 %0, t; }"
        : "=r"(a) : "l"(p));
    return a;
}

__device__ __forceinline__ void cp16(uint32_t dst, const void* src) {
    asm volatile("cp.async.cg.shared.global [%0], [%1], 16;"
                 :: "r"(dst), "l"(src) : "memory");
}
#define CP_COMMIT()  asm volatile("cp.async.commit_group;" ::: "memory")
#define CP_WAIT(n)   asm volatile("cp.async.wait_group %0;" :: "n"(n) : "memory")

#define LDSM4(r0, r1, r2, r3, addr) \
    asm volatile("ldmatrix.sync.aligned.m8n8.x4.shared.b16 {%0,%1,%2,%3}, [%4];" \
                 : "=r"(r0), "=r"(r1), "=r"(r2), "=r"(r3) : "r"(addr))

__device__ __forceinline__ void mma_16x8x16(float* c, const uint32_t* a, const uint32_t* b) {
    asm volatile(
        "mma.sync.aligned.m16n8k16.row.col.f32.f16.f16.f32 "
        "{%0,%1,%2,%3}, {%4,%5,%6,%7}, {%8,%9}, {%0,%1,%2,%3};"
        : "+f"(c[0]), "+f"(c[1]), "+f"(c[2]), "+f"(c[3])
        : "r"(a[0]), "r"(a[1]), "r"(a[2]), "r"(a[3]),
          "r"(b[0]), "r"(b[1]));
}

// Pre-pass: convert x + both weight matrices to fp16 (rn).
__global__ void __launch_bounds__(256)
conv_half(const float4* __restrict__ x, const float4* __restrict__ wq,
          const float4* __restrict__ wp)
{
    const int nx = MROWS * KDIM / 4;   // 15728640
    const int nq = NQKV * KDIM / 4;    //   110592
    const int np = DIM * KDIM / 4;     //    36864
    int i = blockIdx.x * 256 + threadIdx.x;
    float4 v;
    uint2* dst;
    if (i < nx) {
        v = x[i];
        dst = reinterpret_cast<uint2*>(g_xh) + i;
    } else if (i < nx + nq) {
        v = wq[i - nx];
        dst = reinterpret_cast<uint2*>(g_wqh) + (i - nx);
    } else if (i < nx + nq + np) {
        v = wp[i - nx - nq];
        dst = reinterpret_cast<uint2*>(g_wph) + (i - nx - nq);
    } else {
        return;
    }
    union { __half2 h[2]; uint2 u; } pk;
    pk.h[0] = __floats2half2_rn(v.x, v.y);
    pk.h[1] = __floats2half2_rn(v.z, v.w);
    *dst = pk.u;
}

// ====== FP16 GEMM: 128 threads, 4 warps (2x2), warp tile 64x64, CTA 128x128 ======
// C[M,N] = A[M,K] * B[N,K]^T + bias[N];  A, B fp16; C fp32. BK=64, 3-stage cp.async.
// Smem row = 64 fp16 (128B) + 16B pad = 144B.
#define STAGE_BYTES 36864u          // (128*144) * 2  (A half + B half)
#define AB_BYTES    18432u          // 128 * 144
#define ROWB        144u

__global__ void __launch_bounds__(128, 2)
gemm_f16(const __half* __restrict__ A, const __half* __restrict__ B,
         const float* __restrict__ bias, float* __restrict__ C, int N)
{
    extern __shared__ uint32_t dyn[];
    const uint32_t smem_base = smem_u32(dyn);

    const int tid  = threadIdx.x;
    const int warp = tid >> 5;
    const int lane = tid & 31;
    const int lq   = lane >> 2;
    const int lr   = lane & 3;
    const int wm   = (warp >> 1) * 64;
    const int wn   = (warp & 1) * 64;
    const size_t mblk = (size_t)blockIdx.y * 128;
    const int    nblk = blockIdx.x * 128;

    // ldmatrix lane-address offsets (validated mapping, now over 16B = 8 fp16 = half of K16)
    const uint32_t a_off = (uint32_t)(lane & 15) * ROWB + (uint32_t)(lane >> 4) * 16u;
    const uint32_t b_off = ((uint32_t)(lane & 7) + (uint32_t)((lane >> 4) << 3)) * ROWB
                         + (uint32_t)(((lane >> 3) & 1) << 4);

    float acc[4][8][4];
    #pragma unroll
    for (int i = 0; i < 4; i++)
        #pragma unroll
        for (int j = 0; j < 8; j++)
            #pragma unroll
            for (int r = 0; r < 4; r++)
                acc[i][j][r] = 0.0f;

    auto prefetch = [&](int stage, int c) {
        const uint32_t aBase = smem_base + (uint32_t)stage * STAGE_BYTES;
        const uint32_t bBase = aBase + AB_BYTES;
        const int kb = c * BK;
        #pragma unroll
        for (int i = 0; i < 8; i++) {
            int idx = tid + i * 128;         // 0..1023
            int row = idx >> 3;              // 0..127
            int kc  = (idx & 7) << 3;        // fp16 elems: 0,8,...,56
            uint32_t off = (uint32_t)row * ROWB + (uint32_t)((idx & 7) << 4);
            cp16(aBase + off, A + (mblk + row) * KDIM + kb + kc);
            cp16(bBase + off, B + (size_t)(nblk + row) * KDIM + kb + kc);
        }
        CP_COMMIT();
    };

    prefetch(0, 0);
    prefetch(1, 1);

    int s = 0;
    for (int c = 0; c < NCHUNK; c++) {
        if (c < NCHUNK - 1) { CP_WAIT(1); } else { CP_WAIT(0); }
        __syncthreads();

        if (c + 2 < NCHUNK) {
            int ps = s + 2; if (ps >= NSTAGE) ps -= NSTAGE;
            prefetch(ps, c + 2);
        }

        const uint32_t aStage = smem_base + (uint32_t)s * STAGE_BYTES;
        const uint32_t aAddr0 = aStage + (uint32_t)wm * ROWB + a_off;
        const uint32_t bAddr0 = aStage + AB_BYTES + (uint32_t)wn * ROWB + b_off;

        #pragma unroll
        for (int ks = 0; ks < 4; ks++) {          // 4 x K=16 steps per BK=64 chunk
            const uint32_t k0b = (uint32_t)ks * 32u;   // 16 fp16 = 32 bytes
            uint32_t af[4][4], bf[8][2];
            #pragma unroll
            for (int mf = 0; mf < 4; mf++) {
                LDSM4(af[mf][0], af[mf][1], af[mf][2], af[mf][3],
                      aAddr0 + (uint32_t)mf * (16u * ROWB) + k0b);
            }
            #pragma unroll
            for (int p = 0; p < 4; p++) {
                LDSM4(bf[2*p][0], bf[2*p][1], bf[2*p+1][0], bf[2*p+1][1],
                      bAddr0 + (uint32_t)p * (16u * ROWB) + k0b);
            }
            #pragma unroll
            for (int mf = 0; mf < 4; mf++)
                #pragma unroll
                for (int nf = 0; nf < 8; nf++)
                    mma_16x8x16(acc[mf][nf], af[mf], bf[nf]);
        }

        if (++s >= NSTAGE) s -= NSTAGE;
    }

    // Epilogue: bias add + float2 stores (fp32 C)
    #pragma unroll
    for (int mf = 0; mf < 4; mf++) {
        size_t row = mblk + wm + mf * 16 + lq;
        #pragma unroll
        for (int nf = 0; nf < 8; nf++) {
            int col = nblk + wn + nf * 8 + lr * 2;
            float b0 = __ldg(bias + col);
            float b1 = __ldg(bias + col + 1);
            float2 v0 = make_float2(acc[mf][nf][0] + b0, acc[mf][nf][1] + b1);
            float2 v1 = make_float2(acc[mf][nf][2] + b0, acc[mf][nf][3] + b1);
            *reinterpret_cast<float2*>(C + row * (size_t)N + col)       = v0;
            *reinterpret_cast<float2*>(C + (row + 8) * (size_t)N + col) = v1;
        }
    }
}

// ======================= fused attention (fp32 compute, fp16 output) =======================
__global__ void __launch_bounds__(128)
attn_kernel(const float* __restrict__ bias_table)
{
    __shared__ float sQKV[4][3][TT][36];
    __shared__ float sP[4][TT * TT];
    __shared__ float sB[(2 * TT - 1) * NH];

    const int w    = threadIdx.x >> 5;
    const int lane = threadIdx.x & 31;

    for (int i = threadIdx.x; i < (2 * TT - 1) * NH; i += 128)
        sB[i] = bias_table[i];

    const int unit = blockIdx.x * 4 + w;
    const int b = unit / NH;
    const int h = unit - b * NH;

    const float* base = g_qkv + (size_t)(b * TT) * NQKV + h * DH;

    __syncthreads();

    // Stage q,k,v: 240 float4 tasks per warp
    #pragma unroll
    for (int i = 0; i < 8; i++) {
        int task = i * 32 + lane;
        if (task < 240) {
            int row   = task >> 3;
            int c     = task & 7;
            int which = row / 10;
            int t     = row - which * 10;
            float4 v4 = *reinterpret_cast<const float4*>(base + t * NQKV + which * DIM + c * 4);
            *reinterpret_cast<float4*>(&sQKV[w][which][t][c * 4]) = v4;
        }
    }
    __syncwarp();

    const float scale = 0.17677669529663687f;  // 32^-0.5
    #pragma unroll
    for (int e = lane; e < TT * TT; e += 32) {
        int t = e / TT;
        int j = e - t * TT;
        const float2* q2 = reinterpret_cast<const float2*>(&sQKV[w][0][t][0]);
        const float2* k2 = reinterpret_cast<const float2*>(&sQKV[w][1][j][0]);
        float a0 = 0.0f, a1 = 0.0f;
        #pragma unroll
        for (int d = 0; d < 16; d++) {
            float2 qv = q2[d];
            float2 kv = k2[d];
            a0 += qv.x * kv.x;
            a1 += qv.y * kv.y;
        }
        sP[w][e] = (a0 + a1) * scale + sB[(t - j + TT - 1) * NH + h];
    }
    __syncwarp();

    if (lane < TT) {
        float row[TT];
        float m = -1e30f;
        #pragma unroll
        for (int j = 0; j < TT; j++) { row[j] = sP[w][lane * TT + j]; m = fmaxf(m, row[j]); }
        float s = 0.0f;
        #pragma unroll
        for (int j = 0; j < TT; j++) { row[j] = __expf(row[j] - m); s += row[j]; }
        float inv = 1.0f / s;
        #pragma unroll
        for (int j = 0; j < TT; j++) sP[w][lane * TT + j] = row[j] * inv;
    }
    __syncwarp();

    // out[t][d] = sum_j p[t][j] * v[j][d]; write fp16 for GEMM2 (single rounding, = old f2tf)
    __half* outp = g_ath + (size_t)(b * TT) * DIM + h * DH;
    #pragma unroll
    for (int t = 0; t < TT; t++) {
        float a = 0.0f;
        #pragma unroll
        for (int j = 0; j < TT; j++)
            a += sP[w][t * TT + j] * sQKV[w][2][j][lane];
        outp[t * DIM + lane] = __float2half_rn(a);
    }
}

extern "C" void kernel_launch(void* const* d_in, const int* in_sizes, int n_in,
                              void* d_out, int out_size)
{
    (void)in_sizes; (void)n_in; (void)out_size;
    const float* x      = (const float*)d_in[0];   // [16384,10,384]
    const float* qkv_b  = (const float*)d_in[2];   // [1152]
    const float* proj_b = (const float*)d_in[4];   // [384]
    const float* bias_t = (const float*)d_in[5];   // [19,12]
    float* out = (float*)d_out;                    // [163840,384]

    void* pq = nullptr; void* pxh = nullptr; void* pah = nullptr;
    void* pwq = nullptr; void* pwp = nullptr;
    cudaGetSymbolAddress(&pq,  g_qkv);
    cudaGetSymbolAddress(&pxh, g_xh);
    cudaGetSymbolAddress(&pah, g_ath);
    cudaGetSymbolAddress(&pwq, g_wqh);
    cudaGetSymbolAddress(&pwp, g_wph);

    const int smem_bytes = NSTAGE * (int)STAGE_BYTES;   // 110592
    cudaFuncSetAttribute(gemm_f16, cudaFuncAttributeMaxDynamicSharedMemorySize, smem_bytes);

    // 0) Convert x + weights to fp16
    const int ntask = MROWS * KDIM / 4 + NQKV * KDIM / 4 + DIM * KDIM / 4;  // 15876096
    conv_half<<<(ntask + 255) / 256, 256>>>(
        (const float4*)d_in[0], (const float4*)d_in[1], (const float4*)d_in[3]);
    (void)x;

    // 1) qkv = x @ qkv_w^T + qkv_b   (fp16 in, fp32 out)
    dim3 g1(NQKV / 128, MROWS / 128);   // (9, 1280)
    gemm_f16<<<g1, 128, smem_bytes>>>((const __half*)pxh, (const __half*)pwq,
                                      qkv_b, (float*)pq, NQKV);

    // 2) attention, one warp per (b, h); fp32 compute, fp16 output
    attn_kernel<<<(NB * NH) / 4, 128>>>(bias_t);

    // 3) out = att @ proj_w^T + proj_b
    dim3 g2(DIM / 128, MROWS / 128);    // (3, 1280)
    gemm_f16<<<g2, 128, smem_bytes>>>((const __half*)pah, (const __half*)pwp,
                                      proj_b, out, DIM);
}

// round 17
// speedup vs baseline: 1.6680x; 1.0149x over previous
#include <cuda_runtime.h>
#include <cuda_fp16.h>
#include <cstdint>

// Problem constants
#define TT    10
#define NH    12
#define DH    32
#define DIM   384
#define NB    16384
#define MROWS (NB * TT)        // 163840
#define NQKV  1152
#define KDIM  384
#define BK    64
#define NCHUNK (KDIM / BK)     // 6
#define NSTAGE 3

// Scratch (device globals — allocation-free per harness rules)
__device__ __half g_qkvh[(size_t)MROWS * NQKV];  // [163840, 1152] fp16 qkv
__device__ __half g_xh [(size_t)MROWS * KDIM];   // x converted to fp16
__device__ __half g_ath[(size_t)MROWS * DIM];    // attention output, fp16
__device__ __half g_wqh[NQKV * KDIM];            // qkv_w fp16
__device__ __half g_wph[DIM * KDIM];             // proj_w fp16

__device__ __forceinline__ uint32_t smem_u32(const void* p) {
    uint32_t a;
    asm("{ .reg .u64 t; cvta.to.shared.u64 t, %1; cvt.u32.u64 %0, t; }"
        : "=r"(a) : "l"(p));
    return a;
}

__device__ __forceinline__ void cp16(uint32_t dst, const void* src) {
    asm volatile("cp.async.cg.shared.global [%0], [%1], 16;"
                 :: "r"(dst), "l"(src) : "memory");
}
#define CP_COMMIT()  asm volatile("cp.async.commit_group;" ::: "memory")
#define CP_WAIT(n)   asm volatile("cp.async.wait_group %0;" :: "n"(n) : "memory")

#define LDSM4(r0, r1, r2, r3, addr) \
    asm volatile("ldmatrix.sync.aligned.m8n8.x4.shared.b16 {%0,%1,%2,%3}, [%4];" \
                 : "=r"(r0), "=r"(r1), "=r"(r2), "=r"(r3) : "r"(addr))

__device__ __forceinline__ void mma_16x8x16(float* c, const uint32_t* a, const uint32_t* b) {
    asm volatile(
        "mma.sync.aligned.m16n8k16.row.col.f32.f16.f16.f32 "
        "{%0,%1,%2,%3}, {%4,%5,%6,%7}, {%8,%9}, {%0,%1,%2,%3};"
        : "+f"(c[0]), "+f"(c[1]), "+f"(c[2]), "+f"(c[3])
        : "r"(a[0]), "r"(a[1]), "r"(a[2]), "r"(a[3]),
          "r"(b[0]), "r"(b[1]));
}

// Pre-pass: convert x + both weight matrices to fp16 (rn).
__global__ void __launch_bounds__(256)
conv_half(const float4* __restrict__ x, const float4* __restrict__ wq,
          const float4* __restrict__ wp)
{
    const int nx = MROWS * KDIM / 4;
    const int nq = NQKV * KDIM / 4;
    const int np = DIM * KDIM / 4;
    int i = blockIdx.x * 256 + threadIdx.x;
    float4 v;
    uint2* dst;
    if (i < nx) {
        v = x[i];
        dst = reinterpret_cast<uint2*>(g_xh) + i;
    } else if (i < nx + nq) {
        v = wq[i - nx];
        dst = reinterpret_cast<uint2*>(g_wqh) + (i - nx);
    } else if (i < nx + nq + np) {
        v = wp[i - nx - nq];
        dst = reinterpret_cast<uint2*>(g_wph) + (i - nx - nq);
    } else {
        return;
    }
    union { __half2 h[2]; uint2 u; } pk;
    pk.h[0] = __floats2half2_rn(v.x, v.y);
    pk.h[1] = __floats2half2_rn(v.z, v.w);
    *dst = pk.u;
}

// ====== FP16 GEMM: 128 threads, 4 warps (2x2), warp tile 64x64, CTA 128x128 ======
// C[M,N] = A[M,K] * B[N,K]^T + bias[N];  A, B fp16; C = OutT (fp32 or fp16).
// BK=64, 3-stage cp.async. Smem row = 64 fp16 (128B) + 16B pad = 144B.
#define STAGE_BYTES 36864u
#define AB_BYTES    18432u
#define ROWB        144u

template<typename OutT>
__global__ void __launch_bounds__(128, 2)
gemm_f16(const __half* __restrict__ A, const __half* __restrict__ B,
         const float* __restrict__ bias, OutT* __restrict__ C, int N)
{
    extern __shared__ uint32_t dyn[];
    const uint32_t smem_base = smem_u32(dyn);

    const int tid  = threadIdx.x;
    const int warp = tid >> 5;
    const int lane = tid & 31;
    const int lq   = lane >> 2;
    const int lr   = lane & 3;
    const int wm   = (warp >> 1) * 64;
    const int wn   = (warp & 1) * 64;
    const size_t mblk = (size_t)blockIdx.y * 128;
    const int    nblk = blockIdx.x * 128;

    const uint32_t a_off = (uint32_t)(lane & 15) * ROWB + (uint32_t)(lane >> 4) * 16u;
    const uint32_t b_off = ((uint32_t)(lane & 7) + (uint32_t)((lane >> 4) << 3)) * ROWB
                         + (uint32_t)(((lane >> 3) & 1) << 4);

    float acc[4][8][4];
    #pragma unroll
    for (int i = 0; i < 4; i++)
        #pragma unroll
        for (int j = 0; j < 8; j++)
            #pragma unroll
            for (int r = 0; r < 4; r++)
                acc[i][j][r] = 0.0f;

    auto prefetch = [&](int stage, int c) {
        const uint32_t aBase = smem_base + (uint32_t)stage * STAGE_BYTES;
        const uint32_t bBase = aBase + AB_BYTES;
        const int kb = c * BK;
        #pragma unroll
        for (int i = 0; i < 8; i++) {
            int idx = tid + i * 128;
            int row = idx >> 3;
            int kc  = (idx & 7) << 3;
            uint32_t off = (uint32_t)row * ROWB + (uint32_t)((idx & 7) << 4);
            cp16(aBase + off, A + (mblk + row) * KDIM + kb + kc);
            cp16(bBase + off, B + (size_t)(nblk + row) * KDIM + kb + kc);
        }
        CP_COMMIT();
    };

    prefetch(0, 0);
    prefetch(1, 1);

    int s = 0;
    for (int c = 0; c < NCHUNK; c++) {
        if (c < NCHUNK - 1) { CP_WAIT(1); } else { CP_WAIT(0); }
        __syncthreads();

        if (c + 2 < NCHUNK) {
            int ps = s + 2; if (ps >= NSTAGE) ps -= NSTAGE;
            prefetch(ps, c + 2);
        }

        const uint32_t aStage = smem_base + (uint32_t)s * STAGE_BYTES;
        const uint32_t aAddr0 = aStage + (uint32_t)wm * ROWB + a_off;
        const uint32_t bAddr0 = aStage + AB_BYTES + (uint32_t)wn * ROWB + b_off;

        #pragma unroll
        for (int ks = 0; ks < 4; ks++) {
            const uint32_t k0b = (uint32_t)ks * 32u;
            uint32_t af[4][4], bf[8][2];
            #pragma unroll
            for (int mf = 0; mf < 4; mf++) {
                LDSM4(af[mf][0], af[mf][1], af[mf][2], af[mf][3],
                      aAddr0 + (uint32_t)mf * (16u * ROWB) + k0b);
            }
            #pragma unroll
            for (int p = 0; p < 4; p++) {
                LDSM4(bf[2*p][0], bf[2*p][1], bf[2*p+1][0], bf[2*p+1][1],
                      bAddr0 + (uint32_t)p * (16u * ROWB) + k0b);
            }
            #pragma unroll
            for (int mf = 0; mf < 4; mf++)
                #pragma unroll
                for (int nf = 0; nf < 8; nf++)
                    mma_16x8x16(acc[mf][nf], af[mf], bf[nf]);
        }

        if (++s >= NSTAGE) s -= NSTAGE;
    }

    // Epilogue: bias add; fp32 -> float2 stores, fp16 -> __half2 stores
    #pragma unroll
    for (int mf = 0; mf < 4; mf++) {
        size_t row = mblk + wm + mf * 16 + lq;
        #pragma unroll
        for (int nf = 0; nf < 8; nf++) {
            int col = nblk + wn + nf * 8 + lr * 2;
            float b0 = __ldg(bias + col);
            float b1 = __ldg(bias + col + 1);
            if constexpr (sizeof(OutT) == 4) {
                float2 v0 = make_float2(acc[mf][nf][0] + b0, acc[mf][nf][1] + b1);
                float2 v1 = make_float2(acc[mf][nf][2] + b0, acc[mf][nf][3] + b1);
                *reinterpret_cast<float2*>((float*)C + row * (size_t)N + col)       = v0;
                *reinterpret_cast<float2*>((float*)C + (row + 8) * (size_t)N + col) = v1;
            } else {
                __half2 h0 = __floats2half2_rn(acc[mf][nf][0] + b0, acc[mf][nf][1] + b1);
                __half2 h1 = __floats2half2_rn(acc[mf][nf][2] + b0, acc[mf][nf][3] + b1);
                *reinterpret_cast<__half2*>((__half*)C + row * (size_t)N + col)       = h0;
                *reinterpret_cast<__half2*>((__half*)C + (row + 8) * (size_t)N + col) = h1;
            }
        }
    }
}

// ======================= fused attention (fp16 in, fp32 compute, fp16 out) =======================
__global__ void __launch_bounds__(128)
attn_kernel(const float* __restrict__ bias_table)
{
    __shared__ float sQKV[4][3][TT][36];
    __shared__ float sP[4][TT * TT];
    __shared__ float sB[(2 * TT - 1) * NH];

    const int w    = threadIdx.x >> 5;
    const int lane = threadIdx.x & 31;

    for (int i = threadIdx.x; i < (2 * TT - 1) * NH; i += 128)
        sB[i] = bias_table[i];

    const int unit = blockIdx.x * 4 + w;
    const int b = unit / NH;
    const int h = unit - b * NH;

    const __half* base = g_qkvh + (size_t)(b * TT) * NQKV + h * DH;

    __syncthreads();   // sB ready

    // Stage q,k,v: 120 uint4 tasks per warp (each 8 halves -> 8 floats)
    #pragma unroll
    for (int i = 0; i < 4; i++) {
        int task = i * 32 + lane;
        if (task < 120) {
            int row   = task >> 2;          // 0..29
            int c     = task & 3;           // 0..3  (8 halves each)
            int which = row / 10;           // 0=q,1=k,2=v
            int t     = row - which * 10;
            const __half2* src = reinterpret_cast<const __half2*>(
                base + t * NQKV + which * DIM + c * 8);
            uint4 raw = *reinterpret_cast<const uint4*>(src);
            __half2 h0 = *reinterpret_cast<const __half2*>(&raw.x);
            __half2 h1 = *reinterpret_cast<const __half2*>(&raw.y);
            __half2 h2 = *reinterpret_cast<const __half2*>(&raw.z);
            __half2 h3 = *reinterpret_cast<const __half2*>(&raw.w);
            float2 f0 = __half22float2(h0);
            float2 f1 = __half22float2(h1);
            float2 f2 = __half22float2(h2);
            float2 f3 = __half22float2(h3);
            float* dstp = &sQKV[w][which][t][c * 8];
            *reinterpret_cast<float4*>(dstp)     = make_float4(f0.x, f0.y, f1.x, f1.y);
            *reinterpret_cast<float4*>(dstp + 4) = make_float4(f2.x, f2.y, f3.x, f3.y);
        }
    }
    __syncwarp();

    const float scale = 0.17677669529663687f;  // 32^-0.5
    #pragma unroll
    for (int e = lane; e < TT * TT; e += 32) {
        int t = e / TT;
        int j = e - t * TT;
        const float2* q2 = reinterpret_cast<const float2*>(&sQKV[w][0][t][0]);
        const float2* k2 = reinterpret_cast<const float2*>(&sQKV[w][1][j][0]);
        float a0 = 0.0f, a1 = 0.0f;
        #pragma unroll
        for (int d = 0; d < 16; d++) {
            float2 qv = q2[d];
            float2 kv = k2[d];
            a0 += qv.x * kv.x;
            a1 += qv.y * kv.y;
        }
        sP[w][e] = (a0 + a1) * scale + sB[(t - j + TT - 1) * NH + h];
    }
    __syncwarp();

    if (lane < TT) {
        float row[TT];
        float m = -1e30f;
        #pragma unroll
        for (int j = 0; j < TT; j++) { row[j] = sP[w][lane * TT + j]; m = fmaxf(m, row[j]); }
        float s = 0.0f;
        #pragma unroll
        for (int j = 0; j < TT; j++) { row[j] = __expf(row[j] - m); s += row[j]; }
        float inv = 1.0f / s;
        #pragma unroll
        for (int j = 0; j < TT; j++) sP[w][lane * TT + j] = row[j] * inv;
    }
    __syncwarp();

    // out[t][d] = sum_j p[t][j] * v[j][d]; write fp16 for GEMM2
    __half* outp = g_ath + (size_t)(b * TT) * DIM + h * DH;
    #pragma unroll
    for (int t = 0; t < TT; t++) {
        float a = 0.0f;
        #pragma unroll
        for (int j = 0; j < TT; j++)
            a += sP[w][t * TT + j] * sQKV[w][2][j][lane];
        outp[t * DIM + lane] = __float2half_rn(a);
    }
}

extern "C" void kernel_launch(void* const* d_in, const int* in_sizes, int n_in,
                              void* d_out, int out_size)
{
    (void)in_sizes; (void)n_in; (void)out_size;
    const float* qkv_b  = (const float*)d_in[2];   // [1152]
    const float* proj_b = (const float*)d_in[4];   // [384]
    const float* bias_t = (const float*)d_in[5];   // [19,12]
    float* out = (float*)d_out;                    // [163840,384]

    void* pqh = nullptr; void* pxh = nullptr; void* pah = nullptr;
    void* pwq = nullptr; void* pwp = nullptr;
    cudaGetSymbolAddress(&pqh, g_qkvh);
    cudaGetSymbolAddress(&pxh, g_xh);
    cudaGetSymbolAddress(&pah, g_ath);
    cudaGetSymbolAddress(&pwq, g_wqh);
    cudaGetSymbolAddress(&pwp, g_wph);

    const int smem_bytes = NSTAGE * (int)STAGE_BYTES;   // 110592
    cudaFuncSetAttribute(gemm_f16<__half>, cudaFuncAttributeMaxDynamicSharedMemorySize, smem_bytes);
    cudaFuncSetAttribute(gemm_f16<float>,  cudaFuncAttributeMaxDynamicSharedMemorySize, smem_bytes);

    // 0) Convert x + weights to fp16
    const int ntask = MROWS * KDIM / 4 + NQKV * KDIM / 4 + DIM * KDIM / 4;
    conv_half<<<(ntask + 255) / 256, 256>>>(
        (const float4*)d_in[0], (const float4*)d_in[1], (const float4*)d_in[3]);

    // 1) qkv = x @ qkv_w^T + qkv_b   (fp16 in, fp16 out)
    dim3 g1(NQKV / 128, MROWS / 128);   // (9, 1280)
    gemm_f16<__half><<<g1, 128, smem_bytes>>>((const __half*)pxh, (const __half*)pwq,
                                              qkv_b, (__half*)pqh, NQKV);

    // 2) attention, one warp per (b, h); fp32 compute, fp16 output
    attn_kernel<<<(NB * NH) / 4, 128>>>(bias_t);

    // 3) out = att @ proj_w^T + proj_b   (fp16 in, fp32 out)
    dim3 g2(DIM / 128, MROWS / 128);    // (3, 1280)
    gemm_f16<float><<<g2, 128, smem_bytes>>>((const __half*)pah, (const __half*)pwp,
                                             proj_b, out, DIM);
}